// round 15
// baseline (speedup 1.0000x reference)
#include <cuda_runtime.h>
#include <cuda_bf16.h>
#include <math.h>
#include <stdint.h>

#define NTOK   32768
#define C_DIM  384
#define E_NUM  8
#define DFF    1536
#define CAP    8192
#define TM     128
#define TN     128
#define KC     32            // bf16 K elems per chunk
#define RS     40            // smem row stride in halfs (80B) -> conflict-free

// GEMM dynamic smem: 4 plane regions (AH, AL, BH, BL), each 2 stages of 10240 B
#define STG_B   10240
#define OFF_AH  0
#define OFF_AL  20480
#define OFF_BH  40960
#define OFF_BL  61440
#define SMEM_TOT 81920

// kroute dynamic smem layout
#define TOKB     256
#define R_OFF_WR 0
#define R_OFF_WN 12288
#define R_OFF_XS 24576
#define R_SMEM   (24576 + TOKB * 65 * 4)   // 91136

// ---------------- persistent device scratch ----------------
__device__ int   g_texp[NTOK];
__device__ float g_tgate[NTOK];
__device__ int   g_tok[E_NUM * CAP];
__device__ float g_gslot[E_NUM * CAP];
__device__ int   g_count[E_NUM];
__device__ int   g_base[E_NUM];
__device__ __nv_bfloat16 g_xhi[(size_t)NTOK * C_DIM];
__device__ __nv_bfloat16 g_xlo[(size_t)NTOK * C_DIM];
__device__ __nv_bfloat16 g_w1hi[(size_t)E_NUM * DFF * C_DIM];   // [e][n=dff][k=c]
__device__ __nv_bfloat16 g_w1lo[(size_t)E_NUM * DFF * C_DIM];
__device__ __nv_bfloat16 g_w2hi[(size_t)E_NUM * C_DIM * DFF];   // [e][n=c][k=dff]
__device__ __nv_bfloat16 g_w2lo[(size_t)E_NUM * C_DIM * DFF];
__device__ __nv_bfloat16 g_hhi[(size_t)(NTOK + TM) * DFF];      // H hi plane (padded)
__device__ __nv_bfloat16 g_hlo[(size_t)(NTOK + TM) * DFF];

__device__ __forceinline__ uint32_t smem_to_u32(const void* p) {
    uint32_t a;
    asm("{ .reg .u64 t; cvta.to.shared.u64 t, %1; cvt.u32.u64 %0, t; }" : "=r"(a) : "l"(p));
    return a;
}

#define LDSM_X4(R0, R1, R2, R3, ADDR)                                             \
    asm volatile("ldmatrix.sync.aligned.m8n8.x4.shared.b16 {%0,%1,%2,%3}, [%4];"  \
                 : "=r"(R0), "=r"(R1), "=r"(R2), "=r"(R3) : "r"(ADDR))

#define MMA_BF16(D, A0, A1, A2, A3, B0, B1)                                       \
    asm volatile("mma.sync.aligned.m16n8k16.row.col.f32.bf16.bf16.f32 "           \
                 "{%0,%1,%2,%3}, {%4,%5,%6,%7}, {%8,%9}, {%0,%1,%2,%3};"          \
                 : "+f"((D)[0]), "+f"((D)[1]), "+f"((D)[2]), "+f"((D)[3])         \
                 : "r"(A0), "r"(A1), "r"(A2), "r"(A3), "r"(B0), "r"(B1))

#define CP16(SADDR, GPTR)                                                         \
    asm volatile("cp.async.cg.shared.global [%0], [%1], 16;"                      \
                 :: "r"((uint32_t)(SADDR)), "l"(GPTR) : "memory")
#define CP_COMMIT() asm volatile("cp.async.commit_group;" ::: "memory")
#define CP_WAIT0()  asm volatile("cp.async.wait_group 0;" ::: "memory")

// ---- transpose + split, both weights in ONE launch ----
// grid (48, 12, 16): z = e + which*8. which=0: w1 (R=C_DIM,C=DFF) uses (bx,by).
// which=1: w2 (R=DFF,C=C_DIM) uses swapped (by,bx).
__global__ __launch_bounds__(256) void ktrans2(const float* __restrict__ w1,
                                               const float* __restrict__ w2) {
    const int z = blockIdx.z;
    const int which = z >> 3;
    const int e = z & 7;
    const int bx = which ? blockIdx.y : blockIdx.x;
    const int by = which ? blockIdx.x : blockIdx.y;
    const int R = which ? DFF : C_DIM;
    const int C = which ? C_DIM : DFF;
    const float* in = which ? w2 : w1;
    __nv_bfloat16* __restrict__ ohi = which ? g_w2hi : g_w1hi;
    __nv_bfloat16* __restrict__ olo = which ? g_w2lo : g_w1lo;

    __shared__ float tile[32][33];
    const int tx = threadIdx.x, ty = threadIdx.y;   // 32 x 8
    const float* ip = in + (size_t)e * R * C;
#pragma unroll
    for (int i = 0; i < 4; i++)
        tile[ty + 8 * i][tx] = ip[(size_t)(by * 32 + ty + 8 * i) * C + bx * 32 + tx];
    __syncthreads();
    const size_t op = (size_t)e * R * C;
#pragma unroll
    for (int i = 0; i < 4; i++) {
        float v = tile[tx][ty + 8 * i];
        __nv_bfloat16 h = __float2bfloat16(v);
        __nv_bfloat16 l = __float2bfloat16(v - __bfloat162float(h));
        size_t idx = op + (size_t)(bx * 32 + ty + 8 * i) * R + by * 32 + tx;
        ohi[idx] = h;
        olo[idx] = l;
    }
}

// ------ kroute v3: thread-per-token, chunked smem x, broadcast weights ------
// Block = 256 tokens (1 thread each). x staged in 6 chunks of 64 cols (pad 65).
// Weight reads are warp-uniform float4 LDS (broadcast, conflict-free).
// Fuses x->bf16 hi/lo conversion and output zeroing into the staging pass.
__global__ __launch_bounds__(256) void kroute(
        const float* __restrict__ x, const float* __restrict__ noise,
        const float* __restrict__ w_route, const float* __restrict__ b_route,
        const float* __restrict__ w_noise, const float* __restrict__ b_noise,
        float* __restrict__ out) {
    extern __shared__ __align__(16) char rsm[];
    float* swr = (float*)(rsm + R_OFF_WR);
    float* swn = (float*)(rsm + R_OFF_WN);
    float* xs  = (float*)(rsm + R_OFF_XS);
    const int tid = threadIdx.x;
    const int t0  = blockIdx.x * TOKB;

    for (int i = tid; i < E_NUM * C_DIM; i += 256) {
        int c = i >> 3, e = i & 7;              // w_route layout [c][e]
        swr[e * C_DIM + c] = w_route[i];
        swn[e * C_DIM + c] = w_noise[i];
    }

    float ar[E_NUM], an[E_NUM];
#pragma unroll
    for (int e = 0; e < E_NUM; e++) { ar[e] = 0.f; an[e] = 0.f; }

    for (int cc = 0; cc < C_DIM / 64; cc++) {
        __syncthreads();
        // stage 256 tokens x 64 cols; fuse conversion + zeroing (coalesced)
        for (int i = tid; i < TOKB * 64; i += 256) {
            const int tok = i >> 6, c = i & 63;
            const size_t gidx = (size_t)(t0 + tok) * C_DIM + cc * 64 + c;
            const float v = x[gidx];
            xs[tok * 65 + c] = v;
            __nv_bfloat16 h = __float2bfloat16(v);
            g_xhi[gidx] = h;
            g_xlo[gidx] = __float2bfloat16(v - __bfloat162float(h));
            out[gidx] = 0.f;
        }
        __syncthreads();
        const float* xrow = xs + tid * 65;
#pragma unroll
        for (int c4 = 0; c4 < 16; c4++) {
            const float x0 = xrow[c4 * 4 + 0];
            const float x1 = xrow[c4 * 4 + 1];
            const float x2 = xrow[c4 * 4 + 2];
            const float x3 = xrow[c4 * 4 + 3];
#pragma unroll
            for (int e = 0; e < E_NUM; e++) {
                const float4 wr = *(const float4*)&swr[e * C_DIM + cc * 64 + c4 * 4];
                const float4 wn = *(const float4*)&swn[e * C_DIM + cc * 64 + c4 * 4];
                ar[e] = fmaf(x0, wr.x, fmaf(x1, wr.y, fmaf(x2, wr.z, fmaf(x3, wr.w, ar[e]))));
                an[e] = fmaf(x0, wn.x, fmaf(x1, wn.y, fmaf(x2, wn.z, fmaf(x3, wn.w, an[e]))));
            }
        }
    }

    // finalize per token (this thread owns token t0+tid)
    const int t = t0 + tid;
    float ns[E_NUM];
    float best = -INFINITY; int bi = 0;
#pragma unroll
    for (int e = 0; e < E_NUM; e++) {
        float lg = ar[e] + b_route[e];
        float z  = an[e] + b_noise[e];
        float sp = fmaxf(z, 0.f) + log1pf(expf(-fabsf(z)));
        ns[e] = lg + noise[(size_t)t * E_NUM + e] * sp;
        if (ns[e] > best) { best = ns[e]; bi = e; }
    }
    float second = -INFINITY;
#pragma unroll
    for (int e = 0; e < E_NUM; e++)
        if (e != bi && ns[e] > second) second = ns[e];
    g_texp[t]  = bi;
    g_tgate[t] = 1.f / (1.f + expf(second - best));
}

// ------------- ordered compaction (single block, 1024 thr, re-read) -------------
__global__ __launch_bounds__(1024) void kscatter() {
    __shared__ int s[E_NUM][1024];
    __shared__ int stot[E_NUM];
    const int tid = threadIdx.x;
    const int CH  = NTOK / 1024;   // 32
    const int t0  = tid * CH;

    int cnt[E_NUM];
#pragma unroll
    for (int e = 0; e < E_NUM; e++) cnt[e] = 0;
    for (int i = 0; i < CH; i++) cnt[g_texp[t0 + i]]++;
#pragma unroll
    for (int e = 0; e < E_NUM; e++) s[e][tid] = cnt[e];
    __syncthreads();
    for (int off = 1; off < 1024; off <<= 1) {
        int v[E_NUM];
#pragma unroll
        for (int e = 0; e < E_NUM; e++) v[e] = (tid >= off) ? s[e][tid - off] : 0;
        __syncthreads();
#pragma unroll
        for (int e = 0; e < E_NUM; e++) s[e][tid] += v[e];
        __syncthreads();
    }
    int run[E_NUM];
#pragma unroll
    for (int e = 0; e < E_NUM; e++) run[e] = s[e][tid] - cnt[e];
    if (tid < E_NUM) stot[tid] = s[tid][1023];
    __syncthreads();
    if (tid == 0) {
        int b = 0;
        for (int e = 0; e < E_NUM; e++) {
            int c = stot[e] < CAP ? stot[e] : CAP;
            g_count[e] = c;
            g_base[e]  = b;
            b += c;
        }
    }
    for (int i = 0; i < CH; i++) {
        int t = t0 + i;
        int e = g_texp[t];
        int p = run[e]++;
        if (p < CAP) {
            g_tok[e * CAP + p]   = t;
            g_gslot[e * CAP + p] = g_tgate[t];
        }
    }
}

// ========== ldmatrix fragment + mma block (R12-measured best: 64x32 warp tile,
// term-outer ordering, same-acc reuse distance 4) ==========
#define FRAG_MMA_BLOCK(ST)                                                        \
    _Pragma("unroll")                                                             \
    for (int ks = 0; ks < 2; ks++) {                                              \
        uint32_t bh[8], bl[8];                                                    \
        LDSM_X4(bh[0], bh[1], bh[2], bh[3], bBaseH + (ST) + ks * 32);             \
        LDSM_X4(bh[4], bh[5], bh[6], bh[7], bBaseH + (ST) + 1280 + ks * 32);      \
        LDSM_X4(bl[0], bl[1], bl[2], bl[3], bBaseL + (ST) + ks * 32);             \
        LDSM_X4(bl[4], bl[5], bl[6], bl[7], bBaseL + (ST) + 1280 + ks * 32);      \
        _Pragma("unroll")                                                         \
        for (int mt = 0; mt < 4; mt++) {                                          \
            uint32_t ah[4], al[4];                                                \
            LDSM_X4(ah[0], ah[1], ah[2], ah[3],                                   \
                    aBaseH + (ST) + mt * (16 * RS * 2) + ks * 32);                \
            LDSM_X4(al[0], al[1], al[2], al[3],                                   \
                    aBaseL + (ST) + mt * (16 * RS * 2) + ks * 32);                \
            _Pragma("unroll")                                                     \
            for (int j = 0; j < 4; j++)                                           \
                MMA_BF16(acc[mt][j], ah[0], ah[1], ah[2], ah[3],                  \
                         bh[2 * j], bh[2 * j + 1]);                               \
            _Pragma("unroll")                                                     \
            for (int j = 0; j < 4; j++)                                           \
                MMA_BF16(acc[mt][j], al[0], al[1], al[2], al[3],                  \
                         bh[2 * j], bh[2 * j + 1]);                               \
            _Pragma("unroll")                                                     \
            for (int j = 0; j < 4; j++)                                           \
                MMA_BF16(acc[mt][j], ah[0], ah[1], ah[2], ah[3],                  \
                         bl[2 * j], bl[2 * j + 1]);                               \
        }                                                                         \
    }

#define SMEM_DECL extern __shared__ __align__(16) char dsm[];                     \
    const uint32_t sb = smem_to_u32(dsm);

#define FRAG_ADDR_DECL                                                            \
    const uint32_t aBaseH = sb + OFF_AH +                                         \
        (uint32_t)(((wm * 64 + (lane & 15)) * RS + (lane >> 4) * 8) * 2);         \
    const uint32_t aBaseL = sb + OFF_AL +                                         \
        (uint32_t)(((wm * 64 + (lane & 15)) * RS + (lane >> 4) * 8) * 2);         \
    const uint32_t bBaseH = sb + OFF_BH +                                         \
        (uint32_t)(((wn * 32 + (lane & 7) + ((lane >> 4) & 1) * 8) * RS +         \
                    ((lane >> 3) & 1) * 8) * 2);                                  \
    const uint32_t bBaseL = sb + OFF_BL +                                         \
        (uint32_t)(((wn * 32 + (lane & 7) + ((lane >> 4) & 1) * 8) * RS +         \
                    ((lane >> 3) & 1) * 8) * 2);

#define STAGE_IDX_DECL                                                            \
    const int rowS0 = tid >> 2,         chS0 = tid & 3;                           \
    const int rowS1 = (tid + 256) >> 2, chS1 = (tid + 256) & 3;                   \
    const uint32_t sOff0 = (uint32_t)(rowS0 * 80 + chS0 * 16);                    \
    const uint32_t sOff1 = (uint32_t)(rowS1 * 80 + chS1 * 16);

// ----------------- GEMM1: H = relu(Xg @ W1 + b1)^2 (bf16 split out) -----------------
__global__ __launch_bounds__(256, 2) void kgemm1_mma(const float* __restrict__ b1) {
    const int e   = blockIdx.z;
    const int cnt = g_count[e];
    const int m0  = blockIdx.y * TM;
    if (m0 >= cnt) return;
    const int n0  = blockIdx.x * TN;

    SMEM_DECL
    const int tid  = threadIdx.x;
    const int lane = tid & 31;
    const int wid  = tid >> 5;
    const int wm   = wid >> 2;          // 0..1
    const int wn   = wid & 3;           // 0..3
    const int fr   = lane >> 2;         // 0..7
    const int fc   = (lane & 3) * 2;    // 0,2,4,6
    FRAG_ADDR_DECL
    STAGE_IDX_DECL

    const int tk0 = g_tok[e * CAP + m0 + rowS0];
    const int tk1 = g_tok[e * CAP + m0 + rowS1];
    const size_t aG0 = (size_t)tk0 * C_DIM + chS0 * 8;
    const size_t aG1 = (size_t)tk1 * C_DIM + chS1 * 8;
    const size_t bG0 = (size_t)(e * DFF + n0 + rowS0) * C_DIM + chS0 * 8;
    const size_t bG1 = (size_t)(e * DFF + n0 + rowS1) * C_DIM + chS1 * 8;

    float acc[4][4][4];
#pragma unroll
    for (int a = 0; a < 4; a++)
#pragma unroll
        for (int b = 0; b < 4; b++)
#pragma unroll
            for (int c = 0; c < 4; c++) acc[a][b][c] = 0.f;

#define G1_ISSUE(K0, ST)                                                          \
    CP16(sb + OFF_AH + (ST) + sOff0, g_xhi + aG0 + (K0));                         \
    CP16(sb + OFF_AH + (ST) + sOff1, g_xhi + aG1 + (K0));                         \
    CP16(sb + OFF_AL + (ST) + sOff0, g_xlo + aG0 + (K0));                         \
    CP16(sb + OFF_AL + (ST) + sOff1, g_xlo + aG1 + (K0));                         \
    CP16(sb + OFF_BH + (ST) + sOff0, g_w1hi + bG0 + (K0));                        \
    CP16(sb + OFF_BH + (ST) + sOff1, g_w1hi + bG1 + (K0));                        \
    CP16(sb + OFF_BL + (ST) + sOff0, g_w1lo + bG0 + (K0));                        \
    CP16(sb + OFF_BL + (ST) + sOff1, g_w1lo + bG1 + (K0));                        \
    CP_COMMIT();

    G1_ISSUE(0, 0);
    const int NK = C_DIM / KC;   // 12
    for (int kci = 0; kci < NK; kci++) {
        CP_WAIT0();
        __syncthreads();
        const uint32_t st = (uint32_t)(kci & 1) * STG_B;
        if (kci + 1 < NK) { G1_ISSUE((kci + 1) * KC, st ^ STG_B); }
        FRAG_MMA_BLOCK(st);
    }
#undef G1_ISSUE

    const int gb = g_base[e];
    const int c0 = wn * 32 + fc;
    const float* b1p = b1 + (size_t)e * DFF + n0;
    float2 bj[4];
#pragma unroll
    for (int j = 0; j < 4; j++) bj[j] = *(const float2*)(b1p + c0 + j * 8);
#pragma unroll
    for (int mt = 0; mt < 4; mt++) {
#pragma unroll
        for (int hf = 0; hf < 2; hf++) {
            const int r = wm * 64 + mt * 16 + fr + hf * 8;
            const int p = m0 + r;
            if (p < cnt) {
                __nv_bfloat16* hh = g_hhi + (size_t)(gb + p) * DFF + n0;
                __nv_bfloat16* hl = g_hlo + (size_t)(gb + p) * DFF + n0;
#pragma unroll
                for (int j = 0; j < 4; j++) {
                    float v0 = acc[mt][j][hf * 2]     + bj[j].x;
                    float v1 = acc[mt][j][hf * 2 + 1] + bj[j].y;
                    v0 = fmaxf(v0, 0.f); v0 *= v0;
                    v1 = fmaxf(v1, 0.f); v1 *= v1;
                    __nv_bfloat16 h0 = __float2bfloat16(v0);
                    __nv_bfloat16 h1 = __float2bfloat16(v1);
                    __nv_bfloat16 l0 = __float2bfloat16(v0 - __bfloat162float(h0));
                    __nv_bfloat16 l1 = __float2bfloat16(v1 - __bfloat162float(h1));
                    *(__nv_bfloat162*)(hh + c0 + j * 8) = __nv_bfloat162(h0, h1);
                    *(__nv_bfloat162*)(hl + c0 + j * 8) = __nv_bfloat162(l0, l1);
                }
            }
        }
    }
}

// -------- GEMM2: out[tok] = gate * (H @ W2 + b2), scatter --------
__global__ __launch_bounds__(256, 2) void kgemm2_mma(const float* __restrict__ b2,
                                                     float* __restrict__ out) {
    const int e   = blockIdx.z;
    const int cnt = g_count[e];
    const int m0  = blockIdx.y * TM;
    if (m0 >= cnt) return;
    const int n0  = blockIdx.x * TN;

    SMEM_DECL
    const int tid  = threadIdx.x;
    const int lane = tid & 31;
    const int wid  = tid >> 5;
    const int wm   = wid >> 2;
    const int wn   = wid & 3;
    const int fr   = lane >> 2;
    const int fc   = (lane & 3) * 2;
    FRAG_ADDR_DECL
    STAGE_IDX_DECL

    const int gb = g_base[e];
    const size_t aG0 = (size_t)(gb + m0 + rowS0) * DFF + chS0 * 8;
    const size_t aG1 = (size_t)(gb + m0 + rowS1) * DFF + chS1 * 8;
    const size_t bG0 = (size_t)(e * C_DIM + n0 + rowS0) * DFF + chS0 * 8;
    const size_t bG1 = (size_t)(e * C_DIM + n0 + rowS1) * DFF + chS1 * 8;

    float acc[4][4][4];
#pragma unroll
    for (int a = 0; a < 4; a++)
#pragma unroll
        for (int b = 0; b < 4; b++)
#pragma unroll
            for (int c = 0; c < 4; c++) acc[a][b][c] = 0.f;

#define G2_ISSUE(K0, ST)                                                          \
    CP16(sb + OFF_AH + (ST) + sOff0, g_hhi + aG0 + (K0));                         \
    CP16(sb + OFF_AH + (ST) + sOff1, g_hhi + aG1 + (K0));                         \
    CP16(sb + OFF_AL + (ST) + sOff0, g_hlo + aG0 + (K0));                         \
    CP16(sb + OFF_AL + (ST) + sOff1, g_hlo + aG1 + (K0));                         \
    CP16(sb + OFF_BH + (ST) + sOff0, g_w2hi + bG0 + (K0));                        \
    CP16(sb + OFF_BH + (ST) + sOff1, g_w2hi + bG1 + (K0));                        \
    CP16(sb + OFF_BL + (ST) + sOff0, g_w2lo + bG0 + (K0));                        \
    CP16(sb + OFF_BL + (ST) + sOff1, g_w2lo + bG1 + (K0));                        \
    CP_COMMIT();

    G2_ISSUE(0, 0);
    const int NK = DFF / KC;   // 48
    for (int kci = 0; kci < NK; kci++) {
        CP_WAIT0();
        __syncthreads();
        const uint32_t st = (uint32_t)(kci & 1) * STG_B;
        if (kci + 1 < NK) { G2_ISSUE((kci + 1) * KC, st ^ STG_B); }
        FRAG_MMA_BLOCK(st);
    }
#undef G2_ISSUE

    const int c0 = wn * 32 + fc;
    const float* b2p = b2 + (size_t)e * C_DIM + n0;
    float2 bj[4];
#pragma unroll
    for (int j = 0; j < 4; j++) bj[j] = *(const float2*)(b2p + c0 + j * 8);
#pragma unroll
    for (int mt = 0; mt < 4; mt++) {
#pragma unroll
        for (int hf = 0; hf < 2; hf++) {
            const int r = wm * 64 + mt * 16 + fr + hf * 8;
            const int p = m0 + r;
            if (p < cnt) {
                const int tok  = g_tok[e * CAP + p];
                const float gt = g_gslot[e * CAP + p];
                float* op = out + (size_t)tok * C_DIM + n0 + c0;
#pragma unroll
                for (int j = 0; j < 4; j++) {
                    float2 v;
                    v.x = (acc[mt][j][hf * 2]     + bj[j].x) * gt;
                    v.y = (acc[mt][j][hf * 2 + 1] + bj[j].y) * gt;
                    *(float2*)(op + j * 8) = v;
                }
            }
        }
    }
}

// ---------------------------- launch ----------------------------
extern "C" void kernel_launch(void* const* d_in, const int* in_sizes, int n_in,
                              void* d_out, int out_size) {
    const float* x       = (const float*)d_in[0];
    const float* noise   = (const float*)d_in[1];
    const float* w_route = (const float*)d_in[2];
    const float* b_route = (const float*)d_in[3];
    const float* w_noise = (const float*)d_in[4];
    const float* b_noise = (const float*)d_in[5];
    const float* w1      = (const float*)d_in[6];
    const float* b1      = (const float*)d_in[7];
    const float* w2      = (const float*)d_in[8];
    const float* b2      = (const float*)d_in[9];
    float* out = (float*)d_out;

    cudaFuncSetAttribute(kgemm1_mma, cudaFuncAttributeMaxDynamicSharedMemorySize, SMEM_TOT);
    cudaFuncSetAttribute(kgemm2_mma, cudaFuncAttributeMaxDynamicSharedMemorySize, SMEM_TOT);
    cudaFuncSetAttribute(kroute,     cudaFuncAttributeMaxDynamicSharedMemorySize, R_SMEM);

    // kgemm1_mma kept as 4th launch (ncu profiles launch #4).
    kroute<<<NTOK / TOKB, 256, R_SMEM>>>(x, noise, w_route, b_route, w_noise, b_noise, out);
    kscatter<<<1, 1024>>>();
    ktrans2<<<dim3(48, 12, 16), dim3(32, 8)>>>(w1, w2);
    kgemm1_mma<<<dim3(DFF / TN, CAP / TM, E_NUM), 256, SMEM_TOT>>>(b1);
    kgemm2_mma<<<dim3(C_DIM / TN, CAP / TM, E_NUM), 256, SMEM_TOT>>>(b2, out);
}

// round 16
// speedup vs baseline: 1.1603x; 1.1603x over previous
#include <cuda_runtime.h>
#include <cuda_bf16.h>
#include <math.h>
#include <stdint.h>

#define NTOK   32768
#define C_DIM  384
#define E_NUM  8
#define DFF    1536
#define CAP    8192
#define TM     128
#define TN     128
#define KC     32            // bf16 K elems per chunk
#define RS     40            // smem row stride in halfs (80B) -> conflict-free

// GEMM dynamic smem: 4 plane regions (AH, AL, BH, BL), each 2 stages of 10240 B
#define STG_B   10240
#define OFF_AH  0
#define OFF_AL  20480
#define OFF_BH  40960
#define OFF_BL  61440
#define SMEM_TOT 81920

// ---------------- persistent device scratch ----------------
__device__ int   g_texp[NTOK];
__device__ float g_tgate[NTOK];
__device__ int   g_tok[E_NUM * CAP];
__device__ float g_gslot[E_NUM * CAP];
__device__ int   g_count[E_NUM];
__device__ int   g_base[E_NUM];
__device__ __nv_bfloat16 g_xhi[(size_t)NTOK * C_DIM];
__device__ __nv_bfloat16 g_xlo[(size_t)NTOK * C_DIM];
__device__ __nv_bfloat16 g_w1hi[(size_t)E_NUM * DFF * C_DIM];   // [e][n=dff][k=c]
__device__ __nv_bfloat16 g_w1lo[(size_t)E_NUM * DFF * C_DIM];
__device__ __nv_bfloat16 g_w2hi[(size_t)E_NUM * C_DIM * DFF];   // [e][n=c][k=dff]
__device__ __nv_bfloat16 g_w2lo[(size_t)E_NUM * C_DIM * DFF];
__device__ __nv_bfloat16 g_hhi[(size_t)(NTOK + TM) * DFF];      // H hi plane (padded)
__device__ __nv_bfloat16 g_hlo[(size_t)(NTOK + TM) * DFF];

__device__ __forceinline__ uint32_t smem_to_u32(const void* p) {
    uint32_t a;
    asm("{ .reg .u64 t; cvta.to.shared.u64 t, %1; cvt.u32.u64 %0, t; }" : "=r"(a) : "l"(p));
    return a;
}

#define LDSM_X4(R0, R1, R2, R3, ADDR)                                             \
    asm volatile("ldmatrix.sync.aligned.m8n8.x4.shared.b16 {%0,%1,%2,%3}, [%4];"  \
                 : "=r"(R0), "=r"(R1), "=r"(R2), "=r"(R3) : "r"(ADDR))

#define MMA_BF16(D, A0, A1, A2, A3, B0, B1)                                       \
    asm volatile("mma.sync.aligned.m16n8k16.row.col.f32.bf16.bf16.f32 "           \
                 "{%0,%1,%2,%3}, {%4,%5,%6,%7}, {%8,%9}, {%0,%1,%2,%3};"          \
                 : "+f"((D)[0]), "+f"((D)[1]), "+f"((D)[2]), "+f"((D)[3])         \
                 : "r"(A0), "r"(A1), "r"(A2), "r"(A3), "r"(B0), "r"(B1))

#define CP16(SADDR, GPTR)                                                         \
    asm volatile("cp.async.cg.shared.global [%0], [%1], 16;"                      \
                 :: "r"((uint32_t)(SADDR)), "l"(GPTR) : "memory")
#define CP_COMMIT() asm volatile("cp.async.commit_group;" ::: "memory")
#define CP_WAIT0()  asm volatile("cp.async.wait_group 0;" ::: "memory")

// ---- transpose + split, both weights in ONE launch ----
// grid (48, 12, 16): z = e + which*8. which=0: w1 (R=C_DIM,C=DFF) uses (bx,by).
// which=1: w2 (R=DFF,C=C_DIM) uses swapped (by,bx).
__global__ __launch_bounds__(256) void ktrans2(const float* __restrict__ w1,
                                               const float* __restrict__ w2) {
    const int z = blockIdx.z;
    const int which = z >> 3;
    const int e = z & 7;
    const int bx = which ? blockIdx.y : blockIdx.x;
    const int by = which ? blockIdx.x : blockIdx.y;
    const int R = which ? DFF : C_DIM;
    const int C = which ? C_DIM : DFF;
    const float* in = which ? w2 : w1;
    __nv_bfloat16* __restrict__ ohi = which ? g_w2hi : g_w1hi;
    __nv_bfloat16* __restrict__ olo = which ? g_w2lo : g_w1lo;

    __shared__ float tile[32][33];
    const int tx = threadIdx.x, ty = threadIdx.y;   // 32 x 8
    const float* ip = in + (size_t)e * R * C;
#pragma unroll
    for (int i = 0; i < 4; i++)
        tile[ty + 8 * i][tx] = ip[(size_t)(by * 32 + ty + 8 * i) * C + bx * 32 + tx];
    __syncthreads();
    const size_t op = (size_t)e * R * C;
#pragma unroll
    for (int i = 0; i < 4; i++) {
        float v = tile[tx][ty + 8 * i];
        __nv_bfloat16 h = __float2bfloat16(v);
        __nv_bfloat16 l = __float2bfloat16(v - __bfloat162float(h));
        size_t idx = op + (size_t)(bx * 32 + ty + 8 * i) * R + by * 32 + tx;
        ohi[idx] = h;
        olo[idx] = l;
    }
}

// ------ routing + x->bf16 hi/lo conversion + output zeroing (fused, R12 version) ------
__global__ __launch_bounds__(256) void kroute(
        const float* __restrict__ x, const float* __restrict__ noise,
        const float* __restrict__ w_route, const float* __restrict__ b_route,
        const float* __restrict__ w_noise, const float* __restrict__ b_noise,
        float* __restrict__ out) {
    __shared__ float swr[E_NUM * C_DIM];
    __shared__ float swn[E_NUM * C_DIM];
    for (int i = threadIdx.x; i < E_NUM * C_DIM; i += blockDim.x) {
        int c = i >> 3, e = i & 7;
        swr[e * C_DIM + c] = w_route[i];
        swn[e * C_DIM + c] = w_noise[i];
    }
    __syncthreads();
    const int lane = threadIdx.x & 31;
    const int warp = threadIdx.x >> 5;
    const int t = blockIdx.x * 8 + warp;

    float ar[E_NUM], an[E_NUM];
#pragma unroll
    for (int e = 0; e < E_NUM; e++) { ar[e] = 0.f; an[e] = 0.f; }
    const float* xr = x + (size_t)t * C_DIM;
    float* outr = out + (size_t)t * C_DIM;
    __nv_bfloat16* xh = g_xhi + (size_t)t * C_DIM;
    __nv_bfloat16* xl = g_xlo + (size_t)t * C_DIM;
#pragma unroll
    for (int j = 0; j < C_DIM / 32; j++) {
        const int c = j * 32 + lane;
        const float xv = xr[c];
        __nv_bfloat16 h = __float2bfloat16(xv);
        xh[c] = h;
        xl[c] = __float2bfloat16(xv - __bfloat162float(h));
        outr[c] = 0.f;
#pragma unroll
        for (int e = 0; e < E_NUM; e++) {
            ar[e] = fmaf(xv, swr[e * C_DIM + c], ar[e]);
            an[e] = fmaf(xv, swn[e * C_DIM + c], an[e]);
        }
    }
#pragma unroll
    for (int e = 0; e < E_NUM; e++) {
#pragma unroll
        for (int off = 16; off > 0; off >>= 1) {
            ar[e] += __shfl_xor_sync(0xffffffffu, ar[e], off);
            an[e] += __shfl_xor_sync(0xffffffffu, an[e], off);
        }
    }
    if (lane == 0) {
        float ns[E_NUM];
        float best = -INFINITY; int bi = 0;
#pragma unroll
        for (int e = 0; e < E_NUM; e++) {
            float lg = ar[e] + b_route[e];
            float z  = an[e] + b_noise[e];
            float sp = fmaxf(z, 0.f) + log1pf(expf(-fabsf(z)));
            ns[e] = lg + noise[(size_t)t * E_NUM + e] * sp;
            if (ns[e] > best) { best = ns[e]; bi = e; }
        }
        float second = -INFINITY;
#pragma unroll
        for (int e = 0; e < E_NUM; e++)
            if (e != bi && ns[e] > second) second = ns[e];
        g_texp[t]  = bi;
        g_tgate[t] = 1.f / (1.f + expf(second - best));
    }
}

// ------------- ordered compaction (single block, 1024 thr, re-read) -------------
__global__ __launch_bounds__(1024) void kscatter() {
    __shared__ int s[E_NUM][1024];
    __shared__ int stot[E_NUM];
    const int tid = threadIdx.x;
    const int CH  = NTOK / 1024;   // 32
    const int t0  = tid * CH;

    int cnt[E_NUM];
#pragma unroll
    for (int e = 0; e < E_NUM; e++) cnt[e] = 0;
    for (int i = 0; i < CH; i++) cnt[g_texp[t0 + i]]++;
#pragma unroll
    for (int e = 0; e < E_NUM; e++) s[e][tid] = cnt[e];
    __syncthreads();
    for (int off = 1; off < 1024; off <<= 1) {
        int v[E_NUM];
#pragma unroll
        for (int e = 0; e < E_NUM; e++) v[e] = (tid >= off) ? s[e][tid - off] : 0;
        __syncthreads();
#pragma unroll
        for (int e = 0; e < E_NUM; e++) s[e][tid] += v[e];
        __syncthreads();
    }
    int run[E_NUM];
#pragma unroll
    for (int e = 0; e < E_NUM; e++) run[e] = s[e][tid] - cnt[e];
    if (tid < E_NUM) stot[tid] = s[tid][1023];
    __syncthreads();
    if (tid == 0) {
        int b = 0;
        for (int e = 0; e < E_NUM; e++) {
            int c = stot[e] < CAP ? stot[e] : CAP;
            g_count[e] = c;
            g_base[e]  = b;
            b += c;
        }
    }
    for (int i = 0; i < CH; i++) {
        int t = t0 + i;
        int e = g_texp[t];
        int p = run[e]++;
        if (p < CAP) {
            g_tok[e * CAP + p]   = t;
            g_gslot[e * CAP + p] = g_tgate[t];
        }
    }
}

// ========== ldmatrix fragment + mma block (R12-measured best: 64x32 warp tile,
// term-outer ordering, same-acc reuse distance 4) ==========
#define FRAG_MMA_BLOCK(ST)                                                        \
    _Pragma("unroll")                                                             \
    for (int ks = 0; ks < 2; ks++) {                                              \
        uint32_t bh[8], bl[8];                                                    \
        LDSM_X4(bh[0], bh[1], bh[2], bh[3], bBaseH + (ST) + ks * 32);             \
        LDSM_X4(bh[4], bh[5], bh[6], bh[7], bBaseH + (ST) + 1280 + ks * 32);      \
        LDSM_X4(bl[0], bl[1], bl[2], bl[3], bBaseL + (ST) + ks * 32);             \
        LDSM_X4(bl[4], bl[5], bl[6], bl[7], bBaseL + (ST) + 1280 + ks * 32);      \
        _Pragma("unroll")                                                         \
        for (int mt = 0; mt < 4; mt++) {                                          \
            uint32_t ah[4], al[4];                                                \
            LDSM_X4(ah[0], ah[1], ah[2], ah[3],                                   \
                    aBaseH + (ST) + mt * (16 * RS * 2) + ks * 32);                \
            LDSM_X4(al[0], al[1], al[2], al[3],                                   \
                    aBaseL + (ST) + mt * (16 * RS * 2) + ks * 32);                \
            _Pragma("unroll")                                                     \
            for (int j = 0; j < 4; j++)                                           \
                MMA_BF16(acc[mt][j], ah[0], ah[1], ah[2], ah[3],                  \
                         bh[2 * j], bh[2 * j + 1]);                               \
            _Pragma("unroll")                                                     \
            for (int j = 0; j < 4; j++)                                           \
                MMA_BF16(acc[mt][j], al[0], al[1], al[2], al[3],                  \
                         bh[2 * j], bh[2 * j + 1]);                               \
            _Pragma("unroll")                                                     \
            for (int j = 0; j < 4; j++)                                           \
                MMA_BF16(acc[mt][j], ah[0], ah[1], ah[2], ah[3],                  \
                         bl[2 * j], bl[2 * j + 1]);                               \
        }                                                                         \
    }

#define SMEM_DECL extern __shared__ __align__(16) char dsm[];                     \
    const uint32_t sb = smem_to_u32(dsm);

#define FRAG_ADDR_DECL                                                            \
    const uint32_t aBaseH = sb + OFF_AH +                                         \
        (uint32_t)(((wm * 64 + (lane & 15)) * RS + (lane >> 4) * 8) * 2);         \
    const uint32_t aBaseL = sb + OFF_AL +                                         \
        (uint32_t)(((wm * 64 + (lane & 15)) * RS + (lane >> 4) * 8) * 2);         \
    const uint32_t bBaseH = sb + OFF_BH +                                         \
        (uint32_t)(((wn * 32 + (lane & 7) + ((lane >> 4) & 1) * 8) * RS +         \
                    ((lane >> 3) & 1) * 8) * 2);                                  \
    const uint32_t bBaseL = sb + OFF_BL +                                         \
        (uint32_t)(((wn * 32 + (lane & 7) + ((lane >> 4) & 1) * 8) * RS +         \
                    ((lane >> 3) & 1) * 8) * 2);

#define STAGE_IDX_DECL                                                            \
    const int rowS0 = tid >> 2,         chS0 = tid & 3;                           \
    const int rowS1 = (tid + 256) >> 2, chS1 = (tid + 256) & 3;                   \
    const uint32_t sOff0 = (uint32_t)(rowS0 * 80 + chS0 * 16);                    \
    const uint32_t sOff1 = (uint32_t)(rowS1 * 80 + chS1 * 16);

// ----------------- GEMM1: H = relu(Xg @ W1 + b1)^2 (bf16 split out) -----------------
__global__ __launch_bounds__(256, 2) void kgemm1_mma(const float* __restrict__ b1) {
    const int e   = blockIdx.z;
    const int cnt = g_count[e];
    const int m0  = blockIdx.y * TM;
    if (m0 >= cnt) return;
    const int n0  = blockIdx.x * TN;

    SMEM_DECL
    const int tid  = threadIdx.x;
    const int lane = tid & 31;
    const int wid  = tid >> 5;
    const int wm   = wid >> 2;          // 0..1
    const int wn   = wid & 3;           // 0..3
    const int fr   = lane >> 2;         // 0..7
    const int fc   = (lane & 3) * 2;    // 0,2,4,6
    FRAG_ADDR_DECL
    STAGE_IDX_DECL

    const int tk0 = g_tok[e * CAP + m0 + rowS0];
    const int tk1 = g_tok[e * CAP + m0 + rowS1];
    const size_t aG0 = (size_t)tk0 * C_DIM + chS0 * 8;
    const size_t aG1 = (size_t)tk1 * C_DIM + chS1 * 8;
    const size_t bG0 = (size_t)(e * DFF + n0 + rowS0) * C_DIM + chS0 * 8;
    const size_t bG1 = (size_t)(e * DFF + n0 + rowS1) * C_DIM + chS1 * 8;

    float acc[4][4][4];
#pragma unroll
    for (int a = 0; a < 4; a++)
#pragma unroll
        for (int b = 0; b < 4; b++)
#pragma unroll
            for (int c = 0; c < 4; c++) acc[a][b][c] = 0.f;

#define G1_ISSUE(K0, ST)                                                          \
    CP16(sb + OFF_AH + (ST) + sOff0, g_xhi + aG0 + (K0));                         \
    CP16(sb + OFF_AH + (ST) + sOff1, g_xhi + aG1 + (K0));                         \
    CP16(sb + OFF_AL + (ST) + sOff0, g_xlo + aG0 + (K0));                         \
    CP16(sb + OFF_AL + (ST) + sOff1, g_xlo + aG1 + (K0));                         \
    CP16(sb + OFF_BH + (ST) + sOff0, g_w1hi + bG0 + (K0));                        \
    CP16(sb + OFF_BH + (ST) + sOff1, g_w1hi + bG1 + (K0));                        \
    CP16(sb + OFF_BL + (ST) + sOff0, g_w1lo + bG0 + (K0));                        \
    CP16(sb + OFF_BL + (ST) + sOff1, g_w1lo + bG1 + (K0));                        \
    CP_COMMIT();

    G1_ISSUE(0, 0);
    const int NK = C_DIM / KC;   // 12
    for (int kci = 0; kci < NK; kci++) {
        CP_WAIT0();
        __syncthreads();
        const uint32_t st = (uint32_t)(kci & 1) * STG_B;
        if (kci + 1 < NK) { G1_ISSUE((kci + 1) * KC, st ^ STG_B); }
        FRAG_MMA_BLOCK(st);
    }
#undef G1_ISSUE

    const int gb = g_base[e];
    const int c0 = wn * 32 + fc;
    const float* b1p = b1 + (size_t)e * DFF + n0;
    float2 bj[4];
#pragma unroll
    for (int j = 0; j < 4; j++) bj[j] = *(const float2*)(b1p + c0 + j * 8);
#pragma unroll
    for (int mt = 0; mt < 4; mt++) {
#pragma unroll
        for (int hf = 0; hf < 2; hf++) {
            const int r = wm * 64 + mt * 16 + fr + hf * 8;
            const int p = m0 + r;
            if (p < cnt) {
                __nv_bfloat16* hh = g_hhi + (size_t)(gb + p) * DFF + n0;
                __nv_bfloat16* hl = g_hlo + (size_t)(gb + p) * DFF + n0;
#pragma unroll
                for (int j = 0; j < 4; j++) {
                    float v0 = acc[mt][j][hf * 2]     + bj[j].x;
                    float v1 = acc[mt][j][hf * 2 + 1] + bj[j].y;
                    v0 = fmaxf(v0, 0.f); v0 *= v0;
                    v1 = fmaxf(v1, 0.f); v1 *= v1;
                    __nv_bfloat16 h0 = __float2bfloat16(v0);
                    __nv_bfloat16 h1 = __float2bfloat16(v1);
                    __nv_bfloat16 l0 = __float2bfloat16(v0 - __bfloat162float(h0));
                    __nv_bfloat16 l1 = __float2bfloat16(v1 - __bfloat162float(h1));
                    *(__nv_bfloat162*)(hh + c0 + j * 8) = __nv_bfloat162(h0, h1);
                    *(__nv_bfloat162*)(hl + c0 + j * 8) = __nv_bfloat162(l0, l1);
                }
            }
        }
    }
}

// -------- GEMM2: out[tok] = gate * (H @ W2 + b2), scatter --------
__global__ __launch_bounds__(256, 2) void kgemm2_mma(const float* __restrict__ b2,
                                                     float* __restrict__ out) {
    const int e   = blockIdx.z;
    const int cnt = g_count[e];
    const int m0  = blockIdx.y * TM;
    if (m0 >= cnt) return;
    const int n0  = blockIdx.x * TN;

    SMEM_DECL
    const int tid  = threadIdx.x;
    const int lane = tid & 31;
    const int wid  = tid >> 5;
    const int wm   = wid >> 2;
    const int wn   = wid & 3;
    const int fr   = lane >> 2;
    const int fc   = (lane & 3) * 2;
    FRAG_ADDR_DECL
    STAGE_IDX_DECL

    const int gb = g_base[e];
    const size_t aG0 = (size_t)(gb + m0 + rowS0) * DFF + chS0 * 8;
    const size_t aG1 = (size_t)(gb + m0 + rowS1) * DFF + chS1 * 8;
    const size_t bG0 = (size_t)(e * C_DIM + n0 + rowS0) * DFF + chS0 * 8;
    const size_t bG1 = (size_t)(e * C_DIM + n0 + rowS1) * DFF + chS1 * 8;

    float acc[4][4][4];
#pragma unroll
    for (int a = 0; a < 4; a++)
#pragma unroll
        for (int b = 0; b < 4; b++)
#pragma unroll
            for (int c = 0; c < 4; c++) acc[a][b][c] = 0.f;

#define G2_ISSUE(K0, ST)                                                          \
    CP16(sb + OFF_AH + (ST) + sOff0, g_hhi + aG0 + (K0));                         \
    CP16(sb + OFF_AH + (ST) + sOff1, g_hhi + aG1 + (K0));                         \
    CP16(sb + OFF_AL + (ST) + sOff0, g_hlo + aG0 + (K0));                         \
    CP16(sb + OFF_AL + (ST) + sOff1, g_hlo + aG1 + (K0));                         \
    CP16(sb + OFF_BH + (ST) + sOff0, g_w2hi + bG0 + (K0));                        \
    CP16(sb + OFF_BH + (ST) + sOff1, g_w2hi + bG1 + (K0));                        \
    CP16(sb + OFF_BL + (ST) + sOff0, g_w2lo + bG0 + (K0));                        \
    CP16(sb + OFF_BL + (ST) + sOff1, g_w2lo + bG1 + (K0));                        \
    CP_COMMIT();

    G2_ISSUE(0, 0);
    const int NK = DFF / KC;   // 48
    for (int kci = 0; kci < NK; kci++) {
        CP_WAIT0();
        __syncthreads();
        const uint32_t st = (uint32_t)(kci & 1) * STG_B;
        if (kci + 1 < NK) { G2_ISSUE((kci + 1) * KC, st ^ STG_B); }
        FRAG_MMA_BLOCK(st);
    }
#undef G2_ISSUE

    const int c0 = wn * 32 + fc;
    const float* b2p = b2 + (size_t)e * C_DIM + n0;
    float2 bj[4];
#pragma unroll
    for (int j = 0; j < 4; j++) bj[j] = *(const float2*)(b2p + c0 + j * 8);
#pragma unroll
    for (int mt = 0; mt < 4; mt++) {
#pragma unroll
        for (int hf = 0; hf < 2; hf++) {
            const int r = wm * 64 + mt * 16 + fr + hf * 8;
            const int p = m0 + r;
            if (p < cnt) {
                const int tok  = g_tok[e * CAP + p];
                const float gt = g_gslot[e * CAP + p];
                float* op = out + (size_t)tok * C_DIM + n0 + c0;
#pragma unroll
                for (int j = 0; j < 4; j++) {
                    float2 v;
                    v.x = (acc[mt][j][hf * 2]     + bj[j].x) * gt;
                    v.y = (acc[mt][j][hf * 2 + 1] + bj[j].y) * gt;
                    *(float2*)(op + j * 8) = v;
                }
            }
        }
    }
}

// ---------------------------- launch ----------------------------
extern "C" void kernel_launch(void* const* d_in, const int* in_sizes, int n_in,
                              void* d_out, int out_size) {
    const float* x       = (const float*)d_in[0];
    const float* noise   = (const float*)d_in[1];
    const float* w_route = (const float*)d_in[2];
    const float* b_route = (const float*)d_in[3];
    const float* w_noise = (const float*)d_in[4];
    const float* b_noise = (const float*)d_in[5];
    const float* w1      = (const float*)d_in[6];
    const float* b1      = (const float*)d_in[7];
    const float* w2      = (const float*)d_in[8];
    const float* b2      = (const float*)d_in[9];
    float* out = (float*)d_out;

    cudaFuncSetAttribute(kgemm1_mma, cudaFuncAttributeMaxDynamicSharedMemorySize, SMEM_TOT);
    cudaFuncSetAttribute(kgemm2_mma, cudaFuncAttributeMaxDynamicSharedMemorySize, SMEM_TOT);

    // kgemm1_mma kept as 4th launch (ncu profiles launch #4).
    kroute<<<NTOK / 8, 256>>>(x, noise, w_route, b_route, w_noise, b_noise, out);
    kscatter<<<1, 1024>>>();
    ktrans2<<<dim3(48, 12, 16), dim3(32, 8)>>>(w1, w2);
    kgemm1_mma<<<dim3(DFF / TN, CAP / TM, E_NUM), 256, SMEM_TOT>>>(b1);
    kgemm2_mma<<<dim3(C_DIM / TN, CAP / TM, E_NUM), 256, SMEM_TOT>>>(b2, out);
}

// round 17
// speedup vs baseline: 1.4219x; 1.2254x over previous
#include <cuda_runtime.h>
#include <cuda_fp16.h>
#include <math.h>
#include <stdint.h>

#define NTOK   32768
#define C_DIM  384
#define E_NUM  8
#define DFF    1536
#define CAP    8192
#define TM     64
#define TN     128
#define KC     32            // fp16 K elems per chunk
#define RS     40            // smem row stride in halfs (80B) -> conflict-free

#define LO_SCALE   4096.f
#define LO_INV     2.44140625e-4f
#define FTZ_THRESH 6.104e-5f

// dynamic smem: A planes (hi, lo-scaled) 2 stages x 5120, B hi 2 stages x 10240
#define STA_B   5120
#define STB_B   10240
#define OFF_AH  0
#define OFF_AL  10240
#define OFF_BH  20480
#define SMEM_TOT 40960

// ---------------- persistent device scratch ----------------
__device__ int    g_texp[NTOK];
__device__ float  g_tgate[NTOK];
__device__ int    g_tok[E_NUM * CAP];
__device__ float  g_gslot[E_NUM * CAP];
__device__ int    g_count[E_NUM];
__device__ int    g_base[E_NUM];
__device__ __half g_xhi[(size_t)NTOK * C_DIM];
__device__ __half g_xlo[(size_t)NTOK * C_DIM];          // (x - xhi) * 4096, flushed
__device__ __half g_w1hi[(size_t)E_NUM * DFF * C_DIM];  // [e][n=dff][k=c], flushed
__device__ __half g_w2hi[(size_t)E_NUM * C_DIM * DFF];  // [e][n=c][k=dff], flushed
__device__ __half g_hhi[(size_t)(NTOK + TM) * DFF];     // H hi plane (padded)
__device__ __half g_hlo[(size_t)(NTOK + TM) * DFF];     // (h - hhi) * 4096, flushed

__device__ __forceinline__ uint32_t smem_to_u32(const void* p) {
    uint32_t a;
    asm("{ .reg .u64 t; cvta.to.shared.u64 t, %1; cvt.u32.u64 %0, t; }" : "=r"(a) : "l"(p));
    return a;
}
__device__ __forceinline__ __half h_flush(float v) {
    return __float2half(fabsf(v) < FTZ_THRESH ? 0.f : v);
}

#define LDSM_X4(R0, R1, R2, R3, ADDR)                                             \
    asm volatile("ldmatrix.sync.aligned.m8n8.x4.shared.b16 {%0,%1,%2,%3}, [%4];"  \
                 : "=r"(R0), "=r"(R1), "=r"(R2), "=r"(R3) : "r"(ADDR))

#define MMA_F16(D, A0, A1, A2, A3, B0, B1)                                        \
    asm volatile("mma.sync.aligned.m16n8k16.row.col.f32.f16.f16.f32 "             \
                 "{%0,%1,%2,%3}, {%4,%5,%6,%7}, {%8,%9}, {%0,%1,%2,%3};"          \
                 : "+f"((D)[0]), "+f"((D)[1]), "+f"((D)[2]), "+f"((D)[3])         \
                 : "r"(A0), "r"(A1), "r"(A2), "r"(A3), "r"(B0), "r"(B1))

#define CP16(SADDR, GPTR)                                                         \
    asm volatile("cp.async.cg.shared.global [%0], [%1], 16;"                      \
                 :: "r"((uint32_t)(SADDR)), "l"(GPTR) : "memory")
#define CP_COMMIT() asm volatile("cp.async.commit_group;" ::: "memory")
#define CP_WAIT0()  asm volatile("cp.async.wait_group 0;" ::: "memory")

// ---- transpose + fp16-hi split, both weights in ONE launch ----
__global__ __launch_bounds__(256) void ktrans2(const float* __restrict__ w1,
                                               const float* __restrict__ w2) {
    const int z = blockIdx.z;
    const int which = z >> 3;
    const int e = z & 7;
    const int bx = which ? blockIdx.y : blockIdx.x;
    const int by = which ? blockIdx.x : blockIdx.y;
    const int R = which ? DFF : C_DIM;
    const int C = which ? C_DIM : DFF;
    const float* in = which ? w2 : w1;
    __half* __restrict__ ohi = which ? g_w2hi : g_w1hi;

    __shared__ float tile[32][33];
    const int tx = threadIdx.x, ty = threadIdx.y;   // 32 x 8
    const float* ip = in + (size_t)e * R * C;
#pragma unroll
    for (int i = 0; i < 4; i++)
        tile[ty + 8 * i][tx] = ip[(size_t)(by * 32 + ty + 8 * i) * C + bx * 32 + tx];
    __syncthreads();
    const size_t op = (size_t)e * R * C;
#pragma unroll
    for (int i = 0; i < 4; i++) {
        float v = tile[tx][ty + 8 * i];
        size_t idx = op + (size_t)(bx * 32 + ty + 8 * i) * R + by * 32 + tx;
        ohi[idx] = h_flush(v);
    }
}

// ------ routing + x->fp16 hi/lo-scaled conversion + output zeroing (fused) ------
__global__ __launch_bounds__(256) void kroute(
        const float* __restrict__ x, const float* __restrict__ noise,
        const float* __restrict__ w_route, const float* __restrict__ b_route,
        const float* __restrict__ w_noise, const float* __restrict__ b_noise,
        float* __restrict__ out) {
    __shared__ float swr[E_NUM * C_DIM];
    __shared__ float swn[E_NUM * C_DIM];
    for (int i = threadIdx.x; i < E_NUM * C_DIM; i += blockDim.x) {
        int c = i >> 3, e = i & 7;
        swr[e * C_DIM + c] = w_route[i];
        swn[e * C_DIM + c] = w_noise[i];
    }
    __syncthreads();
    const int lane = threadIdx.x & 31;
    const int warp = threadIdx.x >> 5;
    const int t = blockIdx.x * 8 + warp;

    float ar[E_NUM], an[E_NUM];
#pragma unroll
    for (int e = 0; e < E_NUM; e++) { ar[e] = 0.f; an[e] = 0.f; }
    const float* xr = x + (size_t)t * C_DIM;
    float* outr = out + (size_t)t * C_DIM;
    __half* xh = g_xhi + (size_t)t * C_DIM;
    __half* xl = g_xlo + (size_t)t * C_DIM;
#pragma unroll
    for (int j = 0; j < C_DIM / 32; j++) {
        const int c = j * 32 + lane;
        const float xv = xr[c];
        __half h = h_flush(xv);
        xh[c] = h;
        xl[c] = h_flush((xv - __half2float(h)) * LO_SCALE);
        outr[c] = 0.f;
#pragma unroll
        for (int e = 0; e < E_NUM; e++) {
            ar[e] = fmaf(xv, swr[e * C_DIM + c], ar[e]);
            an[e] = fmaf(xv, swn[e * C_DIM + c], an[e]);
        }
    }
#pragma unroll
    for (int e = 0; e < E_NUM; e++) {
#pragma unroll
        for (int off = 16; off > 0; off >>= 1) {
            ar[e] += __shfl_xor_sync(0xffffffffu, ar[e], off);
            an[e] += __shfl_xor_sync(0xffffffffu, an[e], off);
        }
    }
    if (lane == 0) {
        float ns[E_NUM];
        float best = -INFINITY; int bi = 0;
#pragma unroll
        for (int e = 0; e < E_NUM; e++) {
            float lg = ar[e] + b_route[e];
            float z  = an[e] + b_noise[e];
            float sp = fmaxf(z, 0.f) + log1pf(expf(-fabsf(z)));
            ns[e] = lg + noise[(size_t)t * E_NUM + e] * sp;
            if (ns[e] > best) { best = ns[e]; bi = e; }
        }
        float second = -INFINITY;
#pragma unroll
        for (int e = 0; e < E_NUM; e++)
            if (e != bi && ns[e] > second) second = ns[e];
        g_texp[t]  = bi;
        g_tgate[t] = 1.f / (1.f + expf(second - best));
    }
}

// ------------- ordered compaction (single block, 1024 thr, re-read) -------------
__global__ __launch_bounds__(1024) void kscatter() {
    __shared__ int s[E_NUM][1024];
    __shared__ int stot[E_NUM];
    const int tid = threadIdx.x;
    const int CH  = NTOK / 1024;   // 32
    const int t0  = tid * CH;

    int cnt[E_NUM];
#pragma unroll
    for (int e = 0; e < E_NUM; e++) cnt[e] = 0;
    for (int i = 0; i < CH; i++) cnt[g_texp[t0 + i]]++;
#pragma unroll
    for (int e = 0; e < E_NUM; e++) s[e][tid] = cnt[e];
    __syncthreads();
    for (int off = 1; off < 1024; off <<= 1) {
        int v[E_NUM];
#pragma unroll
        for (int e = 0; e < E_NUM; e++) v[e] = (tid >= off) ? s[e][tid - off] : 0;
        __syncthreads();
#pragma unroll
        for (int e = 0; e < E_NUM; e++) s[e][tid] += v[e];
        __syncthreads();
    }
    int run[E_NUM];
#pragma unroll
    for (int e = 0; e < E_NUM; e++) run[e] = s[e][tid] - cnt[e];
    if (tid < E_NUM) stot[tid] = s[tid][1023];
    __syncthreads();
    if (tid == 0) {
        int b = 0;
        for (int e = 0; e < E_NUM; e++) {
            int c = stot[e] < CAP ? stot[e] : CAP;
            g_count[e] = c;
            g_base[e]  = b;
            b += c;
        }
    }
    for (int i = 0; i < CH; i++) {
        int t = t0 + i;
        int e = g_texp[t];
        int p = run[e]++;
        if (p < CAP) {
            g_tok[e * CAP + p]   = t;
            g_gslot[e * CAP + p] = g_tgate[t];
        }
    }
}

// ========== fp16 2-term fragment + mma block (one K-chunk) ==========
// Warp tile 32x32: m = wm*32 + mt*16 (mt 0..1), n = wn*32 + j*8 (j 0..3).
// acc1 += Ahi*Bhi ; acc2 += Alo'*Bhi  (Alo' pre-scaled by 4096, combined in epilogue)
#define FRAG_MMA_BLOCK(STA, STB)                                                  \
    _Pragma("unroll")                                                             \
    for (int ks = 0; ks < 2; ks++) {                                              \
        uint32_t bh[8];                                                           \
        LDSM_X4(bh[0], bh[1], bh[2], bh[3], bBaseH + (STB) + ks * 32);            \
        LDSM_X4(bh[4], bh[5], bh[6], bh[7], bBaseH + (STB) + 1280 + ks * 32);     \
        _Pragma("unroll")                                                         \
        for (int mt = 0; mt < 2; mt++) {                                          \
            uint32_t ah[4], al[4];                                                \
            LDSM_X4(ah[0], ah[1], ah[2], ah[3],                                   \
                    aBaseH + (STA) + mt * 1280 + ks * 32);                        \
            LDSM_X4(al[0], al[1], al[2], al[3],                                   \
                    aBaseL + (STA) + mt * 1280 + ks * 32);                        \
            _Pragma("unroll")                                                     \
            for (int j = 0; j < 4; j++)                                           \
                MMA_F16(acc1[mt][j], ah[0], ah[1], ah[2], ah[3],                  \
                        bh[2 * j], bh[2 * j + 1]);                                \
            _Pragma("unroll")                                                     \
            for (int j = 0; j < 4; j++)                                           \
                MMA_F16(acc2[mt][j], al[0], al[1], al[2], al[3],                  \
                        bh[2 * j], bh[2 * j + 1]);                                \
        }                                                                         \
    }

#define SMEM_DECL extern __shared__ __align__(16) char dsm[];                     \
    const uint32_t sb = smem_to_u32(dsm);

#define FRAG_ADDR_DECL                                                            \
    const uint32_t aBaseH = sb + OFF_AH +                                         \
        (uint32_t)(((wm * 32 + (lane & 15)) * RS + (lane >> 4) * 8) * 2);         \
    const uint32_t aBaseL = sb + OFF_AL +                                         \
        (uint32_t)(((wm * 32 + (lane & 15)) * RS + (lane >> 4) * 8) * 2);         \
    const uint32_t bBaseH = sb + OFF_BH +                                         \
        (uint32_t)(((wn * 32 + (lane & 7) + ((lane >> 4) & 1) * 8) * RS +         \
                    ((lane >> 3) & 1) * 8) * 2);

#define STAGE_IDX_DECL                                                            \
    const int rowS0 = tid >> 2,         chS0 = tid & 3;                           \
    const int rowS1 = (tid + 256) >> 2, chS1 = (tid + 256) & 3;                   \
    const uint32_t sOff0 = (uint32_t)(rowS0 * 80 + chS0 * 16);                    \
    const uint32_t sOff1 = (uint32_t)(rowS1 * 80 + chS1 * 16);

#define ACC_DECL                                                                  \
    float acc1[2][4][4], acc2[2][4][4];                                           \
    _Pragma("unroll")                                                             \
    for (int a = 0; a < 2; a++)                                                   \
        _Pragma("unroll")                                                         \
        for (int b = 0; b < 4; b++)                                               \
            _Pragma("unroll")                                                     \
            for (int c = 0; c < 4; c++) { acc1[a][b][c] = 0.f; acc2[a][b][c] = 0.f; }

// ----------------- GEMM1: H = relu(Xg @ W1 + b1)^2 (fp16 hi/lo' out) -----------------
__global__ __launch_bounds__(256, 2) void kgemm1_mma(const float* __restrict__ b1) {
    const int e   = blockIdx.z;
    const int cnt = g_count[e];
    const int m0  = blockIdx.y * TM;
    if (m0 >= cnt) return;
    const int n0  = blockIdx.x * TN;

    SMEM_DECL
    const int tid  = threadIdx.x;
    const int lane = tid & 31;
    const int wid  = tid >> 5;
    const int wm   = wid >> 2;          // 0..1 (M)
    const int wn   = wid & 3;           // 0..3 (N)
    const int fr   = lane >> 2;         // 0..7
    const int fc   = (lane & 3) * 2;    // 0,2,4,6
    FRAG_ADDR_DECL
    STAGE_IDX_DECL

    const int tkA = g_tok[e * CAP + m0 + rowS0];
    const size_t aG  = (size_t)tkA * C_DIM + chS0 * 8;
    const size_t bG0 = (size_t)(e * DFF + n0 + rowS0) * C_DIM + chS0 * 8;
    const size_t bG1 = (size_t)(e * DFF + n0 + rowS1) * C_DIM + chS1 * 8;

    ACC_DECL

#define G1_ISSUE(K0, STA, STB)                                                    \
    CP16(sb + OFF_AH + (STA) + sOff0, g_xhi + aG + (K0));                         \
    CP16(sb + OFF_AL + (STA) + sOff0, g_xlo + aG + (K0));                         \
    CP16(sb + OFF_BH + (STB) + sOff0, g_w1hi + bG0 + (K0));                       \
    CP16(sb + OFF_BH + (STB) + sOff1, g_w1hi + bG1 + (K0));                       \
    CP_COMMIT();

    G1_ISSUE(0, 0, 0);
    const int NK = C_DIM / KC;   // 12
    for (int kci = 0; kci < NK; kci++) {
        CP_WAIT0();
        __syncthreads();
        const uint32_t stA = (uint32_t)(kci & 1) * STA_B;
        const uint32_t stB = (uint32_t)(kci & 1) * STB_B;
        if (kci + 1 < NK) { G1_ISSUE((kci + 1) * KC, stA ^ STA_B, stB ^ STB_B); }
        FRAG_MMA_BLOCK(stA, stB);
    }
#undef G1_ISSUE

    // epilogue: combine terms, bias + relu^2, emit fp16 hi + scaled lo
    const int gb = g_base[e];
    const int c0 = wn * 32 + fc;
    const float* b1p = b1 + (size_t)e * DFF + n0;
    float2 bj[4];
#pragma unroll
    for (int j = 0; j < 4; j++) bj[j] = *(const float2*)(b1p + c0 + j * 8);
#pragma unroll
    for (int mt = 0; mt < 2; mt++) {
#pragma unroll
        for (int hf = 0; hf < 2; hf++) {
            const int r = wm * 32 + mt * 16 + fr + hf * 8;
            const int p = m0 + r;
            if (p < cnt) {
                __half* hh = g_hhi + (size_t)(gb + p) * DFF + n0;
                __half* hl = g_hlo + (size_t)(gb + p) * DFF + n0;
#pragma unroll
                for (int j = 0; j < 4; j++) {
                    float v0 = acc1[mt][j][hf * 2]     + acc2[mt][j][hf * 2]     * LO_INV + bj[j].x;
                    float v1 = acc1[mt][j][hf * 2 + 1] + acc2[mt][j][hf * 2 + 1] * LO_INV + bj[j].y;
                    v0 = fmaxf(v0, 0.f); v0 *= v0;
                    v1 = fmaxf(v1, 0.f); v1 *= v1;
                    __half h0 = h_flush(v0);
                    __half h1 = h_flush(v1);
                    __half l0 = h_flush((v0 - __half2float(h0)) * LO_SCALE);
                    __half l1 = h_flush((v1 - __half2float(h1)) * LO_SCALE);
                    *(__half2*)(hh + c0 + j * 8) = __halves2half2(h0, h1);
                    *(__half2*)(hl + c0 + j * 8) = __halves2half2(l0, l1);
                }
            }
        }
    }
}

// -------- GEMM2: out[tok] = gate * (H @ W2 + b2), scatter --------
__global__ __launch_bounds__(256, 2) void kgemm2_mma(const float* __restrict__ b2,
                                                     float* __restrict__ out) {
    const int e   = blockIdx.z;
    const int cnt = g_count[e];
    const int m0  = blockIdx.y * TM;
    if (m0 >= cnt) return;
    const int n0  = blockIdx.x * TN;

    SMEM_DECL
    const int tid  = threadIdx.x;
    const int lane = tid & 31;
    const int wid  = tid >> 5;
    const int wm   = wid >> 2;
    const int wn   = wid & 3;
    const int fr   = lane >> 2;
    const int fc   = (lane & 3) * 2;
    FRAG_ADDR_DECL
    STAGE_IDX_DECL

    const int gb = g_base[e];
    const size_t aG  = (size_t)(gb + m0 + rowS0) * DFF + chS0 * 8;
    const size_t bG0 = (size_t)(e * C_DIM + n0 + rowS0) * DFF + chS0 * 8;
    const size_t bG1 = (size_t)(e * C_DIM + n0 + rowS1) * DFF + chS1 * 8;

    ACC_DECL

#define G2_ISSUE(K0, STA, STB)                                                    \
    CP16(sb + OFF_AH + (STA) + sOff0, g_hhi + aG + (K0));                         \
    CP16(sb + OFF_AL + (STA) + sOff0, g_hlo + aG + (K0));                         \
    CP16(sb + OFF_BH + (STB) + sOff0, g_w2hi + bG0 + (K0));                       \
    CP16(sb + OFF_BH + (STB) + sOff1, g_w2hi + bG1 + (K0));                       \
    CP_COMMIT();

    G2_ISSUE(0, 0, 0);
    const int NK = DFF / KC;   // 48
    for (int kci = 0; kci < NK; kci++) {
        CP_WAIT0();
        __syncthreads();
        const uint32_t stA = (uint32_t)(kci & 1) * STA_B;
        const uint32_t stB = (uint32_t)(kci & 1) * STB_B;
        if (kci + 1 < NK) { G2_ISSUE((kci + 1) * KC, stA ^ STA_B, stB ^ STB_B); }
        FRAG_MMA_BLOCK(stA, stB);
    }
#undef G2_ISSUE

    const int c0 = wn * 32 + fc;
    const float* b2p = b2 + (size_t)e * C_DIM + n0;
    float2 bj[4];
#pragma unroll
    for (int j = 0; j < 4; j++) bj[j] = *(const float2*)(b2p + c0 + j * 8);
#pragma unroll
    for (int mt = 0; mt < 2; mt++) {
#pragma unroll
        for (int hf = 0; hf < 2; hf++) {
            const int r = wm * 32 + mt * 16 + fr + hf * 8;
            const int p = m0 + r;
            if (p < cnt) {
                const int tok  = g_tok[e * CAP + p];
                const float gt = g_gslot[e * CAP + p];
                float* op = out + (size_t)tok * C_DIM + n0 + c0;
#pragma unroll
                for (int j = 0; j < 4; j++) {
                    float2 v;
                    v.x = (acc1[mt][j][hf * 2]     + acc2[mt][j][hf * 2]     * LO_INV + bj[j].x) * gt;
                    v.y = (acc1[mt][j][hf * 2 + 1] + acc2[mt][j][hf * 2 + 1] * LO_INV + bj[j].y) * gt;
                    *(float2*)(op + j * 8) = v;
                }
            }
        }
    }
}

// ---------------------------- launch ----------------------------
extern "C" void kernel_launch(void* const* d_in, const int* in_sizes, int n_in,
                              void* d_out, int out_size) {
    const float* x       = (const float*)d_in[0];
    const float* noise   = (const float*)d_in[1];
    const float* w_route = (const float*)d_in[2];
    const float* b_route = (const float*)d_in[3];
    const float* w_noise = (const float*)d_in[4];
    const float* b_noise = (const float*)d_in[5];
    const float* w1      = (const float*)d_in[6];
    const float* b1      = (const float*)d_in[7];
    const float* w2      = (const float*)d_in[8];
    const float* b2      = (const float*)d_in[9];
    float* out = (float*)d_out;

    cudaFuncSetAttribute(kgemm1_mma, cudaFuncAttributeMaxDynamicSharedMemorySize, SMEM_TOT);
    cudaFuncSetAttribute(kgemm2_mma, cudaFuncAttributeMaxDynamicSharedMemorySize, SMEM_TOT);

    // kgemm1_mma kept as 4th launch (ncu profiles launch #4).
    kroute<<<NTOK / 8, 256>>>(x, noise, w_route, b_route, w_noise, b_noise, out);
    kscatter<<<1, 1024>>>();
    ktrans2<<<dim3(48, 12, 16), dim3(32, 8)>>>(w1, w2);
    kgemm1_mma<<<dim3(DFF / TN, CAP / TM, E_NUM), 256, SMEM_TOT>>>(b1);
    kgemm2_mma<<<dim3(C_DIM / TN, CAP / TM, E_NUM), 256, SMEM_TOT>>>(b2, out);
}